// round 7
// baseline (speedup 1.0000x reference)
#include <cuda_runtime.h>
#include <cuda_fp16.h>
#include <cstdint>

// ============================================================================
// Efficient_SKAN_Base as ONE fused GEMM: out[b,o] = sum_k A[b,k]*W[k,o] + bias[o]
//   A[b, 0:128]       = silu(x[b,:])
//   A[b, 128j : +128] = sin(grid[j-1] * x[b,:])   j=1..8
// R7: B weights pre-shuffled into per-thread MMA fragment order -> consumers
// LDG.128 them straight to registers (no smem for B). A: 3-stage smem ring
// with split named barriers (producer warps 8-15 run ahead; consumer warps
// 0-7 pure LDSM+HMMA).
// ============================================================================

#define B_ROWS   131072
#define NUM_F    8
#define NCHUNK   9
#define ROW_H    136              // halves per A K-row (128 + 8 pad)
#define ROW_B    (ROW_H * 2)      // 272 B -> conflict-free LDSM/STS
#define CHUNK_BYTES (128 * ROW_B) // 34816 per 128x128 fp16 A tile
#define NSTAGE   3

// Fragment-ordered folded weights: [c][wn][ks][i][lane] -> uint4 (16B)
//   per (c,wn): 8 ks * 4 i * 32 lanes = 1024 uint4 = 16KB
__device__ uint4 g_W[NCHUNK * 2 * 1024];
__device__ float g_bias[128];

#define S_TOTAL (NSTAGE * CHUNK_BYTES)   // 104448 B

// ---------------- helpers ----------------
static __device__ __forceinline__ uint32_t smem_u32(const void* p) {
    uint32_t a;
    asm("{ .reg .u64 t; cvta.to.shared.u64 t, %1; cvt.u32.u64 %0, t; }" : "=r"(a) : "l"(p));
    return a;
}
static __device__ __forceinline__ uint32_t h2u(__half2 h) {
    return *reinterpret_cast<uint32_t*>(&h);
}
static __device__ __forceinline__ void ldsm4(uint32_t* r, uint32_t addr) {
    asm volatile("ldmatrix.sync.aligned.m8n8.x4.shared.b16 {%0,%1,%2,%3}, [%4];"
                 : "=r"(r[0]), "=r"(r[1]), "=r"(r[2]), "=r"(r[3]) : "r"(addr));
}
static __device__ __forceinline__ void hmma(float* d, const uint32_t* a,
                                            uint32_t b0, uint32_t b1) {
    asm("mma.sync.aligned.m16n8k16.row.col.f32.f16.f16.f32 "
        "{%0,%1,%2,%3},{%4,%5,%6,%7},{%8,%9},{%0,%1,%2,%3};"
        : "+f"(d[0]), "+f"(d[1]), "+f"(d[2]), "+f"(d[3])
        : "r"(a[0]), "r"(a[1]), "r"(a[2]), "r"(a[3]), "r"(b0), "r"(b1));
}
static __device__ __forceinline__ void bar_sync(int id) {
    asm volatile("bar.sync %0, 512;" :: "r"(id) : "memory");
}
static __device__ __forceinline__ void bar_arrive(int id) {
    asm volatile("bar.arrive %0, 512;" :: "r"(id) : "memory");
}
static __device__ __forceinline__ void membar_cta() {
    asm volatile("membar.cta;" ::: "memory");
}

// ============================================================================
// Prep: fold coef & scale_sp into weights, fp16, write MMA b-fragment order.
// u32 index decode: j=idx&3, lane=(idx>>2)&31, i=(idx>>7)&3, ks=(idx>>9)&7,
//                   wn=(idx>>12)&1, c=idx>>13.
// tile t = i*2 + (j>>1); reg = j&1.
//   n = wn*64 + t*8 + (lane>>2)
//   k = ks*16 + (lane&3)*2 + reg*8     (u32 = half2{W[n][k], W[n][k+1]})
// ============================================================================
__global__ void skan_prep(const float* __restrict__ base_w,
                          const float* __restrict__ scale_sp,
                          const float* __restrict__ coef,
                          const float* __restrict__ conv_w,
                          const float* __restrict__ conv_b) {
    int idx = blockIdx.x * 256 + threadIdx.x;
    const int total = NCHUNK * 2 * 1024 * 4;   // 73728 u32
    if (idx < total) {
        int j = idx & 3, lane = (idx >> 2) & 31, i = (idx >> 7) & 3;
        int ks = (idx >> 9) & 7, wn = (idx >> 12) & 1, c = idx >> 13;
        int t = i * 2 + (j >> 1);
        int n = wn * 64 + t * 8 + (lane >> 2);
        int k = ks * 16 + (lane & 3) * 2 + (j & 1) * 8;
        float v0, v1;
        if (c == 0) {
            v0 = base_w[n * 128 + k];
            v1 = base_w[n * 128 + k + 1];
        } else {
            int f = c - 1;
            v0 = conv_w[f * 16384 + n * 128 + k]     * coef[k * NUM_F + f]       * scale_sp[n];
            v1 = conv_w[f * 16384 + n * 128 + k + 1] * coef[(k + 1) * NUM_F + f] * scale_sp[n];
        }
        reinterpret_cast<uint32_t*>(g_W)[idx] = h2u(__floats2half2_rn(v0, v1));
    }
    if (idx < 128) {
        float s = 0.f;
        #pragma unroll
        for (int f = 0; f < NUM_F; f++) s += conv_b[f * 128 + idx];
        g_bias[idx] = s * scale_sp[idx];
    }
}

// ============================================================================
__global__ __launch_bounds__(512, 1) void skan_main(const float* __restrict__ x,
                                                    const float* __restrict__ grid,
                                                    float* __restrict__ out) {
    extern __shared__ char smem[];
    const int tid = threadIdx.x;
    const int lane = tid & 31, wid = tid >> 5;
    const size_t m0 = (size_t)blockIdx.x * 128;
    const uint32_t sb = smem_u32(smem);

    if (wid >= 8) {
        // ---------------- PRODUCER: warps 8-15 (feature gen only) -----------
        const int ptid = tid - 256;
        const int grow = ptid & 127;
        const int kh = ptid >> 7;

        float4 xv[16];
        {
            const float4* xg =
                reinterpret_cast<const float4*>(x + (m0 + grow) * 128 + kh * 64);
            #pragma unroll
            for (int j = 0; j < 16; j++) xv[j] = xg[j];
        }

        #pragma unroll 1
        for (int c = 0; c < NCHUNK; c++) {
            const int s = c % NSTAGE;
            if (c >= NSTAGE) bar_sync(4 + s);      // wait stage free
            char* arow = smem + s * CHUNK_BYTES + grow * ROW_B + kh * 128;
            if (c == 0) {
                #pragma unroll
                for (int ks = 0; ks < 8; ks++) {
                    float4 x0 = xv[2 * ks], x1 = xv[2 * ks + 1];
                    float v0 = __fdividef(x0.x, 1.f + __expf(-x0.x));
                    float v1 = __fdividef(x0.y, 1.f + __expf(-x0.y));
                    float v2 = __fdividef(x0.z, 1.f + __expf(-x0.z));
                    float v3 = __fdividef(x0.w, 1.f + __expf(-x0.w));
                    float v4 = __fdividef(x1.x, 1.f + __expf(-x1.x));
                    float v5 = __fdividef(x1.y, 1.f + __expf(-x1.y));
                    float v6 = __fdividef(x1.z, 1.f + __expf(-x1.z));
                    float v7 = __fdividef(x1.w, 1.f + __expf(-x1.w));
                    uint4 pk;
                    pk.x = h2u(__floats2half2_rn(v0, v1));
                    pk.y = h2u(__floats2half2_rn(v2, v3));
                    pk.z = h2u(__floats2half2_rn(v4, v5));
                    pk.w = h2u(__floats2half2_rn(v6, v7));
                    *(uint4*)(arow + ks * 16) = pk;
                }
            } else {
                const float g = __ldg(grid + c - 1);
                #pragma unroll
                for (int ks = 0; ks < 8; ks++) {
                    float4 x0 = xv[2 * ks], x1 = xv[2 * ks + 1];
                    uint4 pk;
                    pk.x = h2u(__floats2half2_rn(__sinf(g * x0.x), __sinf(g * x0.y)));
                    pk.y = h2u(__floats2half2_rn(__sinf(g * x0.z), __sinf(g * x0.w)));
                    pk.z = h2u(__floats2half2_rn(__sinf(g * x1.x), __sinf(g * x1.y)));
                    pk.w = h2u(__floats2half2_rn(__sinf(g * x1.z), __sinf(g * x1.w)));
                    *(uint4*)(arow + ks * 16) = pk;
                }
            }
            membar_cta();            // make STS visible before arrival
            bar_arrive(1 + s);       // stage full
        }
    } else {
        // ---------------- CONSUMER: warps 0-7 (LDSM A + LDG B + HMMA) -------
        const int wm = wid >> 1, wn = wid & 1;   // warp tile 32x64
        const uint32_t alo =
            (uint32_t)(wm * 32 + ((lane >> 3) & 1) * 8 + (lane & 7)) * ROW_B
            + ((lane >> 4) & 1) * 16;

        // B fragment stream (uint4 units): block (c*2+wn)*1024, ks stride 128
        const uint4* bch = g_W + (size_t)wn * 1024 + lane;

        uint4 Bc[4], Bn[4];
        #pragma unroll
        for (int i = 0; i < 4; i++) Bc[i] = __ldg(bch + i * 32);   // c=0, ks=0

        float acc[2][8][4];
        #pragma unroll
        for (int mt = 0; mt < 2; mt++)
            #pragma unroll
            for (int nt = 0; nt < 8; nt++)
                #pragma unroll
                for (int v = 0; v < 4; v++) acc[mt][nt][v] = 0.f;

        #pragma unroll 1
        for (int c = 0; c < NCHUNK; c++) {
            const int s = c % NSTAGE;
            const uint32_t abuf = sb + s * CHUNK_BYTES;
            bar_sync(1 + s);                     // wait stage full
            #pragma unroll
            for (int ks = 0; ks < 8; ks++) {
                uint32_t a0r[4], a1r[4];
                ldsm4(a0r, abuf + alo + ks * 32);
                ldsm4(a1r, abuf + alo + 16 * ROW_B + ks * 32);
                const bool last = (c == NCHUNK - 1) && (ks == 7);
                if (!last) {    // prefetch next k-step's B fragments
                    const uint4* nb = (ks < 7) ? (bch + (ks + 1) * 128)
                                               : (bch + 2048);   // next chunk ks0
                    #pragma unroll
                    for (int i = 0; i < 4; i++) Bn[i] = __ldg(nb + i * 32);
                }
                #pragma unroll
                for (int t = 0; t < 8; t++) {
                    const uint32_t* bp = reinterpret_cast<const uint32_t*>(&Bc[t >> 1]);
                    const uint32_t b0 = bp[(t & 1) * 2], b1 = bp[(t & 1) * 2 + 1];
                    hmma(acc[0][t], a0r, b0, b1);
                    hmma(acc[1][t], a1r, b0, b1);
                }
                if (!last) {
                    Bc[0] = Bn[0]; Bc[1] = Bn[1]; Bc[2] = Bn[2]; Bc[3] = Bn[3];
                }
            }
            bar_arrive(4 + s);                   // stage free
            bch += 2048;                         // next chunk's fragment block
        }

        // epilogue: + bias, float2 stores
        const int l4 = lane >> 2, q = lane & 3;
        #pragma unroll
        for (int nt = 0; nt < 8; nt++) {
            const int col = wn * 64 + nt * 8 + q * 2;
            const float bx = __ldg(g_bias + col);
            const float by = __ldg(g_bias + col + 1);
            #pragma unroll
            for (int mt = 0; mt < 2; mt++) {
                const size_t r = m0 + wm * 32 + mt * 16 + l4;
                float2 v0 = make_float2(acc[mt][nt][0] + bx, acc[mt][nt][1] + by);
                float2 v1 = make_float2(acc[mt][nt][2] + bx, acc[mt][nt][3] + by);
                *(float2*)(out + r * 128 + col)       = v0;
                *(float2*)(out + (r + 8) * 128 + col) = v1;
            }
        }
    }
}

// ============================================================================
extern "C" void kernel_launch(void* const* d_in, const int* in_sizes, int n_in,
                              void* d_out, int out_size) {
    (void)in_sizes; (void)n_in; (void)out_size;
    const float* x        = (const float*)d_in[0];
    const float* grid     = (const float*)d_in[1];
    const float* base_w   = (const float*)d_in[2];
    const float* scale_sp = (const float*)d_in[3];
    const float* coef     = (const float*)d_in[4];
    const float* conv_w   = (const float*)d_in[5];
    const float* conv_b   = (const float*)d_in[6];
    float* out = (float*)d_out;

    cudaFuncSetAttribute(skan_main, cudaFuncAttributeMaxDynamicSharedMemorySize, S_TOTAL);

    const int prep_total = NCHUNK * 2 * 1024 * 4;
    skan_prep<<<(prep_total + 255) / 256, 256>>>(base_w, scale_sp, coef, conv_w, conv_b);
    skan_main<<<B_ROWS / 128, 512, S_TOTAL>>>(x, grid, out);
}